// round 3
// baseline (speedup 1.0000x reference)
#include <cuda_runtime.h>
#include <cstdint>

// Problem constants
#define NUM_E 8
#define NUM_T 8192
#define NUM_K 2048
#define NUM_N 2048
#define NUM_G 16
#define PACKF 8

constexpr int BM = 128;
constexpr int BN = 128;
constexpr int BK = 32;
constexpr int THREADS = 256;

// ---------------- static device scratch (no allocations allowed) ----------------
__device__ int   g_counts[NUM_E];
__device__ int   g_offsets[NUM_E];
__device__ int   g_cursor[NUM_E];
__device__ int   g_sorted[NUM_T];
__device__ float g_bias[NUM_E * NUM_G * NUM_N];   // -zp * scale, 1 MB

// ---------------- prep kernels ----------------
__global__ void k_zero() {
    if (threadIdx.x < NUM_E) { g_counts[threadIdx.x] = 0; g_cursor[threadIdx.x] = 0; }
}

__global__ void k_count(const int* __restrict__ expert_ids) {
    int t = blockIdx.x * blockDim.x + threadIdx.x;
    if (t < NUM_T) atomicAdd(&g_counts[expert_ids[t]], 1);
}

__global__ void k_prefix() {
    if (threadIdx.x == 0) {
        int acc = 0;
        for (int e = 0; e < NUM_E; e++) { g_offsets[e] = acc; acc += g_counts[e]; }
    }
}

__global__ void k_scatter(const int* __restrict__ expert_ids) {
    int t = blockIdx.x * blockDim.x + threadIdx.x;
    if (t < NUM_T) {
        int e = expert_ids[t];
        int p = atomicAdd(&g_cursor[e], 1);
        g_sorted[g_offsets[e] + p] = t;
    }
}

__global__ void k_bias(const float* __restrict__ wscale, const int* __restrict__ zp) {
    int i = blockIdx.x * blockDim.x + threadIdx.x;
    if (i < NUM_E * NUM_G * NUM_N) g_bias[i] = -wscale[i] * (float)zp[i];
}

// ---------------- helpers ----------------
__device__ __forceinline__ unsigned f2tf32(float x) {
    unsigned r;
    asm("cvt.rna.tf32.f32 %0, %1;" : "=r"(r) : "f"(x));
    return r;
}

#define MMA_TF32(d, a, b)                                                      \
    asm volatile(                                                              \
        "mma.sync.aligned.m16n8k8.row.col.f32.tf32.tf32.f32 "                  \
        "{%0,%1,%2,%3}, {%4,%5,%6,%7}, {%8,%9}, {%0,%1,%2,%3};"                \
        : "+f"(d[0]), "+f"(d[1]), "+f"(d[2]), "+f"(d[3])                       \
        : "r"(a[0]), "r"(a[1]), "r"(a[2]), "r"(a[3]), "r"(b[0]), "r"(b[1]))

// ---------------- grouped GEMM ----------------
// grid: (N/BN, T/BM, E). Blocks whose m-tile exceeds this expert's token count exit.
__global__ __launch_bounds__(THREADS, 2)
void k_gemm(const float* __restrict__ state,       // [T, K]
            const int*   __restrict__ wpacked,     // [E, K/8, N]
            const float* __restrict__ wscale,      // [E, G, N]
            const int*   __restrict__ g_idx,       // [K]
            float*       __restrict__ out)         // [T, N]
{
    const int e     = blockIdx.z;
    const int cnt   = g_counts[e];
    const int mbase = blockIdx.y * BM;
    if (mbase >= cnt) return;
    const int off   = g_offsets[e];
    const int nbase = blockIdx.x * BN;

    __shared__ float As[BM][BK + 4];    // stride 36: conflict-free A-frag reads
    __shared__ float Bs[BK][BN + 8];    // stride 136: conflict-free B-frag reads
    __shared__ int   toks[BM];
    __shared__ int   gsh[BK];

    const int tid  = threadIdx.x;
    const int wid  = tid >> 5;
    const int lane = tid & 31;
    const int wm   = (wid >> 2) * 64;   // warp M offset (2 warp-rows)
    const int wn   = (wid & 3) * 32;    // warp N offset (4 warp-cols)
    const int grp  = lane >> 2;         // 0..7
    const int tig  = lane & 3;          // 0..3

    if (tid < BM) {
        int gm = mbase + tid;
        toks[tid] = (gm < cnt) ? g_sorted[off + gm] : g_sorted[off];  // clamp: dup row, never stored
    }

    float acc[4][4][4];
#pragma unroll
    for (int mi = 0; mi < 4; mi++)
#pragma unroll
        for (int ni = 0; ni < 4; ni++)
#pragma unroll
            for (int r = 0; r < 4; r++) acc[mi][ni][r] = 0.0f;

    const int*   wp_e = wpacked + (size_t)e * (NUM_K / PACKF) * NUM_N;
    const float* ws_e = wscale  + (size_t)e * NUM_G * NUM_N;
    const float* wb_e = g_bias  + (size_t)e * NUM_G * NUM_N;

    const int arow = tid >> 3;        // 0..31
    const int akq  = (tid & 7) * 4;   // 0,4,...,28

    __syncthreads();   // toks visible

    for (int k0 = 0; k0 < NUM_K; k0 += BK) {
        // ---- g_idx chunk ----
        if (tid < BK) gsh[tid] = g_idx[k0 + tid];

        // ---- A tile: gather 128 rows x 32 floats, convert to tf32 ----
#pragma unroll
        for (int p = 0; p < 4; p++) {
            int r = arow + p * 32;
            const float4 v = *reinterpret_cast<const float4*>(
                &state[(size_t)toks[r] * NUM_K + k0 + akq]);
            As[r][akq + 0] = __uint_as_float(f2tf32(v.x));
            As[r][akq + 1] = __uint_as_float(f2tf32(v.y));
            As[r][akq + 2] = __uint_as_float(f2tf32(v.z));
            As[r][akq + 3] = __uint_as_float(f2tf32(v.w));
        }
        __syncthreads();   // gsh visible for dequant below (and As half-barrier merged)

        // ---- B tile: dequant 4 packed rows x 128 cols -> 32 x 128 tf32 ----
        const int kp0 = k0 >> 3;   // k0 / 8
#pragma unroll
        for (int i = 0; i < 2; i++) {
            int w    = tid + i * THREADS;      // 0..511
            int prow = w >> 7;                 // 0..3
            int n    = w & 127;
            unsigned q32 = (unsigned)wp_e[(size_t)(kp0 + prow) * NUM_N + nbase + n];
#pragma unroll
            for (int j = 0; j < 8; j++) {
                int   kl = prow * 8 + j;
                int   g  = gsh[kl];
                float s  = ws_e[g * NUM_N + nbase + n];
                float b  = wb_e[g * NUM_N + nbase + n];
                float q  = (float)((q32 >> (4 * j)) & 15u);
                Bs[kl][n] = __uint_as_float(f2tf32(fmaf(q, s, b)));
            }
        }
        __syncthreads();

        // ---- MMA: 4 k8-steps ----
#pragma unroll
        for (int ks = 0; ks < BK; ks += 8) {
            unsigned af[4][4], bf[4][2];
#pragma unroll
            for (int mi = 0; mi < 4; mi++) {
                int mr = wm + mi * 16 + grp;
                af[mi][0] = __float_as_uint(As[mr    ][ks + tig    ]);
                af[mi][1] = __float_as_uint(As[mr + 8][ks + tig    ]);
                af[mi][2] = __float_as_uint(As[mr    ][ks + tig + 4]);
                af[mi][3] = __float_as_uint(As[mr + 8][ks + tig + 4]);
            }
#pragma unroll
            for (int ni = 0; ni < 4; ni++) {
                int nc = wn + ni * 8 + grp;
                bf[ni][0] = __float_as_uint(Bs[ks + tig    ][nc]);
                bf[ni][1] = __float_as_uint(Bs[ks + tig + 4][nc]);
            }
#pragma unroll
            for (int mi = 0; mi < 4; mi++)
#pragma unroll
                for (int ni = 0; ni < 4; ni++)
                    MMA_TF32(acc[mi][ni], af[mi], bf[ni]);
        }
        __syncthreads();   // guard smem overwrite next iteration
    }

    // ---- epilogue: scatter rows to out[token][n] ----
#pragma unroll
    for (int mi = 0; mi < 4; mi++) {
        int rl0 = wm + mi * 16 + grp;        // local row for c0/c1
        int rl1 = rl0 + 8;                   // local row for c2/c3
        bool v0 = (mbase + rl0) < cnt;
        bool v1 = (mbase + rl1) < cnt;
        int tok0 = toks[rl0];
        int tok1 = toks[rl1];
#pragma unroll
        for (int ni = 0; ni < 4; ni++) {
            int c = nbase + wn + ni * 8 + tig * 2;
            if (v0) {
                float2 val = make_float2(acc[mi][ni][0], acc[mi][ni][1]);
                *reinterpret_cast<float2*>(&out[(size_t)tok0 * NUM_N + c]) = val;
            }
            if (v1) {
                float2 val = make_float2(acc[mi][ni][2], acc[mi][ni][3]);
                *reinterpret_cast<float2*>(&out[(size_t)tok1 * NUM_N + c]) = val;
            }
        }
    }
}

// ---------------- launch ----------------
extern "C" void kernel_launch(void* const* d_in, const int* in_sizes, int n_in,
                              void* d_out, int out_size) {
    const float* state      = (const float*)d_in[0];
    const int*   wpacked    = (const int*)  d_in[1];
    const float* wscale     = (const float*)d_in[2];
    const int*   zp         = (const int*)  d_in[3];
    const int*   g_idx      = (const int*)  d_in[4];
    const int*   expert_ids = (const int*)  d_in[5];
    float*       out        = (float*)d_out;

    k_zero<<<1, 32>>>();
    k_count<<<NUM_T / 256, 256>>>(expert_ids);
    k_prefix<<<1, 32>>>();
    k_scatter<<<NUM_T / 256, 256>>>(expert_ids);
    k_bias<<<(NUM_E * NUM_G * NUM_N) / 256, 256>>>(wscale, zp);

    dim3 grid(NUM_N / BN, NUM_T / BM, NUM_E);
    k_gemm<<<grid, THREADS>>>(state, wpacked, wscale, g_idx, out);
}

// round 4
// speedup vs baseline: 2.8992x; 2.8992x over previous
#include <cuda_runtime.h>
#include <cuda_fp16.h>
#include <cstdint>

#define NUM_E 8
#define NUM_T 8192
#define NUM_K 2048
#define NUM_N 2048
#define NUM_G 16

constexpr int BM = 128;
constexpr int BN = 128;
constexpr int BK = 32;       // k per main-loop iter
constexpr int BKP = BK / 2;  // k-pairs (half2) per iter = 16
constexpr int PAD = 4;       // uint row stride 20 -> conflict-free fragment reads
constexpr int THREADS = 256;
constexpr int KITERS = NUM_K / BK;  // 64

// ---------------- static device scratch (no allocations allowed) ----------------
__device__ int    g_counts[NUM_E];
__device__ int    g_offsets[NUM_E];
__device__ int    g_sorted[NUM_T];
__device__ __half g_Ah[(size_t)NUM_T * NUM_K];          // state fp16, 32 MB
__device__ __half g_Bh[(size_t)NUM_E * NUM_N * NUM_K];  // dequant W [e][n][k], 64 MB
__device__ uint2  g_zs[NUM_E * NUM_G * (NUM_N / 2)];    // {half2(1024+zp), half2(scale)}

// ---------------- routing (single block) ----------------
__global__ void k_route(const int* __restrict__ expert_ids) {
    __shared__ int cnt[NUM_E], cur[NUM_E];
    int t = threadIdx.x;
    if (t < NUM_E) cnt[t] = 0;
    __syncthreads();
    for (int i = t; i < NUM_T; i += blockDim.x) atomicAdd(&cnt[expert_ids[i]], 1);
    __syncthreads();
    if (t == 0) {
        int acc = 0;
        for (int e = 0; e < NUM_E; e++) {
            g_counts[e] = cnt[e]; g_offsets[e] = acc; cur[e] = acc;
            acc += cnt[e];
        }
    }
    __syncthreads();
    for (int i = t; i < NUM_T; i += blockDim.x) {
        int p = atomicAdd(&cur[expert_ids[i]], 1);
        g_sorted[p] = i;
    }
}

// ---------------- zp/scale tables ----------------
__global__ void k_zs(const float* __restrict__ ws, const int* __restrict__ zp) {
    int idx = blockIdx.x * blockDim.x + threadIdx.x;       // over E*G*N/2
    int np = idx & (NUM_N / 2 - 1);
    int eg = idx / (NUM_N / 2);
    const float* wsp = ws + (size_t)eg * NUM_N + 2 * np;
    const int*   zpp = zp + (size_t)eg * NUM_N + 2 * np;
    // fp16 bits of (1024+z), z in [0,15], are exactly 0x6400 | z
    unsigned z2 = (0x6400u | (unsigned)zpp[0]) | ((0x6400u | (unsigned)zpp[1]) << 16);
    __half2 s2h = __floats2half2_rn(wsp[0], wsp[1]);
    uint2 v; v.x = z2; v.y = *reinterpret_cast<unsigned*>(&s2h);
    g_zs[idx] = v;
}

// ---------------- state fp32 -> fp16 ----------------
__global__ void k_aprep(const float* __restrict__ state) {
    size_t i = (size_t)blockIdx.x * blockDim.x + threadIdx.x;  // over T*K/8
    const float4* s4 = reinterpret_cast<const float4*>(state);
    float4 a = s4[i * 2], b = s4[i * 2 + 1];
    __half2 h0 = __floats2half2_rn(a.x, a.y), h1 = __floats2half2_rn(a.z, a.w);
    __half2 h2 = __floats2half2_rn(b.x, b.y), h3 = __floats2half2_rn(b.z, b.w);
    uint4 o;
    o.x = *reinterpret_cast<unsigned*>(&h0);
    o.y = *reinterpret_cast<unsigned*>(&h1);
    o.z = *reinterpret_cast<unsigned*>(&h2);
    o.w = *reinterpret_cast<unsigned*>(&h3);
    reinterpret_cast<uint4*>(g_Ah)[i] = o;
}

// ---------------- W expand: packed uint4 -> fp16 [e][n][k] ----------------
// grid: (kb=4, nb=8, e=8), block 256. Block covers 512 k's x 256 n's.
__global__ void k_wexpand(const int* __restrict__ wp, const int* __restrict__ gidx) {
    __shared__ uint2 zs[NUM_G][128];
    __shared__ int   gsh[512];
    const int e  = blockIdx.z;
    const int nb = blockIdx.y;
    const int kb = blockIdx.x;
    const int t  = threadIdx.x;

    for (int i = t; i < NUM_G * 128; i += THREADS) {
        int g = i >> 7, np = i & 127;
        zs[g][np] = g_zs[(e * NUM_G + g) * (NUM_N / 2) + nb * 128 + np];
    }
    for (int i = t; i < 512; i += THREADS) gsh[i] = gidx[kb * 512 + i];
    __syncthreads();

    const int npl = t & 127;             // n-pair within block
    const int kh  = t >> 7;              // 0/1: word-row half
    const int npg = nb * 128 + npl;      // global n-pair
    const uint2* wp2 = reinterpret_cast<const uint2*>(wp + (size_t)e * (NUM_K / 8) * NUM_N);

    for (int p = 0; p < 32; p++) {
        const int rowl = kh * 32 + p;        // word-row in block (0..63)
        const int rowg = kb * 64 + rowl;     // global word-row
        uint2 w = wp2[(size_t)rowg * (NUM_N / 2) + npg];
        unsigned pr[8];
#pragma unroll
        for (int j = 0; j < 8; j++) {
            uint2 zsv = zs[gsh[rowl * 8 + j]][npl];
            unsigned x0 = w.x >> (4 * j), x1 = w.y >> (4 * j);
            unsigned h2 = ((x0 & 15u) | 0x6400u) | (((x1 & 15u) | 0x6400u) << 16);
            __half2 v = __hsub2(*reinterpret_cast<__half2*>(&h2),
                                *reinterpret_cast<__half2*>(&zsv.x));   // exact q - zp
            v = __hmul2(v, *reinterpret_cast<__half2*>(&zsv.y));
            pr[j] = *reinterpret_cast<unsigned*>(&v);
        }
        // transpose n-pairs -> k-pairs
        unsigned u0[4], u1[4];
#pragma unroll
        for (int q = 0; q < 4; q++) {
            u0[q] = __byte_perm(pr[2 * q], pr[2 * q + 1], 0x5410);  // n0: (k2q, k2q+1)
            u1[q] = __byte_perm(pr[2 * q], pr[2 * q + 1], 0x7632);  // n1
        }
        size_t base = ((size_t)e * NUM_N + 2 * npg) * NUM_K + (size_t)rowg * 8;  // halfs
        *reinterpret_cast<uint4*>(&g_Bh[base])          = make_uint4(u0[0], u0[1], u0[2], u0[3]);
        *reinterpret_cast<uint4*>(&g_Bh[base + NUM_K])  = make_uint4(u1[0], u1[1], u1[2], u1[3]);
    }
}

// ---------------- cp.async helpers ----------------
__device__ __forceinline__ void cpa16(void* dst, const void* src) {
    unsigned d = (unsigned)__cvta_generic_to_shared(dst);
    asm volatile("cp.async.cg.shared.global [%0], [%1], 16;" :: "r"(d), "l"(src));
}
__device__ __forceinline__ void cp_commit() { asm volatile("cp.async.commit_group;"); }
template <int N>
__device__ __forceinline__ void cp_wait() { asm volatile("cp.async.wait_group %0;" :: "n"(N)); }

#define MMA_F16(d, a, b)                                                        \
    asm volatile(                                                               \
        "mma.sync.aligned.m16n8k16.row.col.f32.f16.f16.f32 "                    \
        "{%0,%1,%2,%3}, {%4,%5,%6,%7}, {%8,%9}, {%0,%1,%2,%3};"                 \
        : "+f"(d[0]), "+f"(d[1]), "+f"(d[2]), "+f"(d[3])                        \
        : "r"(a[0]), "r"(a[1]), "r"(a[2]), "r"(a[3]), "r"(b[0]), "r"(b[1]))

// ---------------- grouped GEMM, fp16 in / fp32 acc, 2-stage cp.async ----------------
__global__ __launch_bounds__(THREADS, 2)
void k_gemm(float* __restrict__ out) {
    const int e     = blockIdx.z;
    const int cnt   = g_counts[e];
    const int mbase = blockIdx.y * BM;
    if (mbase >= cnt) return;
    const int off   = g_offsets[e];
    const int nbase = blockIdx.x * BN;

    // uint rows of k-pairs; stride 20 -> conflict-free fragment reads
    __shared__ __align__(16) unsigned As2[2][BM][BKP + PAD];
    __shared__ __align__(16) unsigned Bs2[2][BN][BKP + PAD];
    __shared__ int toks[BM];

    const int tid  = threadIdx.x;
    const int wid  = tid >> 5;
    const int lane = tid & 31;
    const int wm   = (wid >> 2) * 64;
    const int wn   = (wid & 3) * 32;
    const int grp  = lane >> 3;          // unused placeholder (kept minimal below)
    const int g8   = lane >> 2;          // 0..7 (octet row/col)
    const int tig  = lane & 3;           // 0..3

    if (tid < BM) {
        int gm = mbase + tid;
        toks[tid] = (gm < cnt) ? g_sorted[off + gm] : g_sorted[off];
    }
    __syncthreads();

    const int r  = tid >> 1;                       // 0..127 (row for loads)
    const int kc = (tid & 1) * 2;                  // 16B chunk base: 0 or 2

    const __half* Bg = g_Bh + ((size_t)e * NUM_N + nbase) * NUM_K;

    // load one BK-slab into stage s
    auto load_stage = [&](int s, int k0) {
        // A: 128 rows x 32 halfs; each thread 2x16B
        const __half* arow = g_Ah + (size_t)toks[r] * NUM_K + k0;
        cpa16(&As2[s][r][kc * 4],        arow + kc * 8);
        cpa16(&As2[s][r][(kc + 1) * 4],  arow + (kc + 1) * 8);
        // B: 128 n-rows x 32 halfs
        const __half* brow = Bg + (size_t)r * NUM_K + k0;
        cpa16(&Bs2[s][r][kc * 4],        brow + kc * 8);
        cpa16(&Bs2[s][r][(kc + 1) * 4],  brow + (kc + 1) * 8);
    };

    float acc[4][4][4];
#pragma unroll
    for (int mi = 0; mi < 4; mi++)
#pragma unroll
        for (int ni = 0; ni < 4; ni++)
#pragma unroll
            for (int q = 0; q < 4; q++) acc[mi][ni][q] = 0.0f;

    load_stage(0, 0);
    cp_commit();

    for (int kt = 0; kt < KITERS; kt++) {
        const int s = kt & 1;
        if (kt + 1 < KITERS) {
            load_stage(s ^ 1, (kt + 1) * BK);
            cp_commit();
            cp_wait<1>();
        } else {
            cp_wait<0>();
        }
        __syncthreads();

#pragma unroll
        for (int ks = 0; ks < 2; ks++) {            // two k16 steps
            const int kp = ks * 8;
            unsigned af[4][4], bf[4][2];
#pragma unroll
            for (int mi = 0; mi < 4; mi++) {
                int mr = wm + mi * 16 + g8;
                af[mi][0] = As2[s][mr    ][kp + tig];
                af[mi][1] = As2[s][mr + 8][kp + tig];
                af[mi][2] = As2[s][mr    ][kp + tig + 4];
                af[mi][3] = As2[s][mr + 8][kp + tig + 4];
            }
#pragma unroll
            for (int ni = 0; ni < 4; ni++) {
                int nc = wn + ni * 8 + g8;
                bf[ni][0] = Bs2[s][nc][kp + tig];
                bf[ni][1] = Bs2[s][nc][kp + tig + 4];
            }
#pragma unroll
            for (int mi = 0; mi < 4; mi++)
#pragma unroll
                for (int ni = 0; ni < 4; ni++)
                    MMA_F16(acc[mi][ni], af[mi], bf[ni]);
        }
        __syncthreads();
    }

    // epilogue: scatter rows to out[token][n]
#pragma unroll
    for (int mi = 0; mi < 4; mi++) {
        int rl0 = wm + mi * 16 + g8;
        int rl1 = rl0 + 8;
        bool v0 = (mbase + rl0) < cnt;
        bool v1 = (mbase + rl1) < cnt;
        int tok0 = toks[rl0];
        int tok1 = toks[rl1];
#pragma unroll
        for (int ni = 0; ni < 4; ni++) {
            int c = nbase + wn + ni * 8 + tig * 2;
            if (v0) *reinterpret_cast<float2*>(&out[(size_t)tok0 * NUM_N + c]) =
                make_float2(acc[mi][ni][0], acc[mi][ni][1]);
            if (v1) *reinterpret_cast<float2*>(&out[(size_t)tok1 * NUM_N + c]) =
                make_float2(acc[mi][ni][2], acc[mi][ni][3]);
        }
    }
}

// ---------------- launch ----------------
extern "C" void kernel_launch(void* const* d_in, const int* in_sizes, int n_in,
                              void* d_out, int out_size) {
    const float* state      = (const float*)d_in[0];
    const int*   wpacked    = (const int*)  d_in[1];
    const float* wscale     = (const float*)d_in[2];
    const int*   zp         = (const int*)  d_in[3];
    const int*   g_idx      = (const int*)  d_in[4];
    const int*   expert_ids = (const int*)  d_in[5];
    float*       out        = (float*)d_out;

    k_route<<<1, 1024>>>(expert_ids);
    k_zs<<<(NUM_E * NUM_G * (NUM_N / 2)) / 256, 256>>>(wscale, zp);
    k_aprep<<<(NUM_T * NUM_K / 8) / 256, 256>>>(state);
    k_wexpand<<<dim3(4, 8, NUM_E), THREADS>>>(wpacked, g_idx);

    dim3 grid(NUM_N / BN, NUM_T / BM, NUM_E);
    k_gemm<<<grid, THREADS>>>(out);
}